// round 6
// baseline (speedup 1.0000x reference)
#include <cuda_runtime.h>
#include <math.h>
#include <stdint.h>

#define NB 32
#define HW 1024

#define CKC 169   // x_ul_b channels
#define CQC 166   // ul_b channels
#define COC 160   // ul channels
#define KDIM 16
#define VDIM 80

typedef unsigned long long u64;

// ---------------- scratch (static device memory; no allocations) ----------------
__device__ float g_cat [(size_t)NB * CKC * HW];   // x_ul_b  [n,169,1024]; ul_b = view +3*HW
__device__ float g_h   [(size_t)NB * CKC * HW];   // GRN hidden (largest C=169)
__device__ float g_gout[(size_t)NB * CKC * HW];   // GRN output (reused per branch)
__device__ float g_keys[(size_t)NB * KDIM * HW];
__device__ float g_quer[(size_t)NB * KDIM * HW];
__device__ float g_vals[(size_t)NB * VDIM * HW];
__device__ float g_att [(size_t)NB * HW * HW];    // presoftmax -> att weights (in place)
__device__ float g_attv[(size_t)NB * VDIM * HW];

__device__ __forceinline__ float eluf(float v) { return v > 0.f ? v : (expf(v) - 1.f); }

// packed fp32x2 FMA: d = a*b + d  (both halves)
__device__ __forceinline__ void fma2(u64& d, u64 a, u64 b) {
    asm("fma.rn.f32x2 %0, %1, %2, %0;" : "+l"(d) : "l"(a), "l"(b));
}
__device__ __forceinline__ void unpack2(float& lo, float& hi, u64 v) {
    asm("mov.b64 {%0, %1}, %2;" : "=f"(lo), "=f"(hi) : "l"(v));
}

// ---------------- concat inputs into [n,169,hw] ----------------
__global__ void build_cat_kernel(const float* __restrict__ x, const float* __restrict__ ul,
                                 const float* __restrict__ b, float* __restrict__ cat) {
    long idx = (long)blockIdx.x * blockDim.x + threadIdx.x;
    const long total = (long)NB * CKC * HW;
    if (idx >= total) return;
    int p = (int)(idx % HW);
    int c = (int)((idx / HW) % CKC);
    int n = (int)(idx / ((long)CKC * HW));
    float v;
    if (c < 3)        v = x [((long)n * 3   + c        ) * HW + p];
    else if (c < 163) v = ul[((long)n * 160 + (c - 3)  ) * HW + p];
    else              v = b [((long)n * 6   + (c - 163)) * HW + p];
    cat[idx] = v;
}

// ============ Big GEMM (f32x2): Out = W*concat_elu(X) [+ W2*concat_elu(X2)] + bias(+bias2) ============
// Tile 64 out x 128 px, 256 threads, per-thread 8 out x 4 px (2 packed pairs).
// W duplicated {w,w} in smem so LDS.128 yields packed broadcast operands.

#define GEMM_LOAD_CHUNK(kk)                                                          \
    {                                                                                \
        const float* Xs; const float* Ws; int Ci; long xs; int c0;                   \
        if ((kk) < nk1) { Xs = X;  Ws = W;  Ci = Cin;  xs = xStride;  c0 = (kk) * 16; } \
        else            { Xs = X2; Ws = W2; Ci = Cin2; xs = x2Stride; c0 = ((kk) - nk1) * 16; } \
        const int  cbase = c0 + (fw & 15);                                           \
        const int  wcol  = (fw < 16) ? cbase : (Ci + cbase);                         \
        const bool cok   = cbase < Ci;                                               \
        _Pragma("unroll")                                                            \
        for (int i = 0; i < 8; ++i) {                                                \
            const int o = o0 + o8 + i * 8;                                           \
            wreg[i] = (cok && o < Cout) ? Ws[(long)o * (2 * Ci) + wcol] : 0.f;       \
        }                                                                            \
        const float* Xn = Xs + (long)n * xs;                                         \
        _Pragma("unroll")                                                            \
        for (int i = 0; i < 8; ++i) {                                                \
            const int c = c0 + c2 + i * 2;                                           \
            xreg[i] = (c < Ci) ? Xn[(long)c * HW + p0 + px] : 0.f;                   \
        }                                                                            \
    }

#define GEMM_STORE_CHUNK()                                                           \
    {                                                                                \
        _Pragma("unroll")                                                            \
        for (int i = 0; i < 8; ++i) {                                                \
            float2 wd = {wreg[i], wreg[i]};                                          \
            *reinterpret_cast<float2*>(&sW[fw][(o8 + i * 8) * 2]) = wd;              \
        }                                                                            \
        _Pragma("unroll")                                                            \
        for (int i = 0; i < 8; ++i) {                                                \
            const int   cl = c2 + i * 2;                                             \
            const float v  = xreg[i];                                                \
            sX[cl][px]      = eluf(v);                                               \
            sX[cl + 16][px] = eluf(-v);                                              \
        }                                                                            \
    }

__global__ void __launch_bounds__(256)
gemm_celu_kernel(const float* __restrict__ X, long xStride, int Cin,
                 const float* __restrict__ W,
                 const float* __restrict__ X2, long x2Stride, int Cin2,
                 const float* __restrict__ W2,
                 const float* __restrict__ bias, const float* __restrict__ bias2,
                 int Cout, float* __restrict__ Out, long oStride) {
    __shared__ __align__(16) float sW[32][136];   // duplicated pairs: out o at cols 2o,2o+1
    __shared__ __align__(16) float sX[32][128];
    const int tid = threadIdx.x;
    const int n  = blockIdx.y >> 3;
    const int p0 = (blockIdx.y & 7) * 128;
    const int o0 = blockIdx.x * 64;

    const int fw  = tid & 31;    // W: feature
    const int o8  = tid >> 5;    // W: out sub
    const int px  = tid & 127;   // X: pixel
    const int c2  = tid >> 7;    // X: channel sub
    const int ox  = tid & 7;     // compute: out group (8 rows each)
    const int pxg = tid >> 3;    // compute: px group (4 px each)

    const int nk1 = (Cin + 15) >> 4;
    const int nk2 = W2 ? ((Cin2 + 15) >> 4) : 0;
    const int nk  = nk1 + nk2;

    float wreg[8], xreg[8];
    u64 acc[8][2];
    #pragma unroll
    for (int i = 0; i < 8; ++i) { acc[i][0] = 0ull; acc[i][1] = 0ull; }

    GEMM_LOAD_CHUNK(0);
    GEMM_STORE_CHUNK();
    __syncthreads();

    for (int k = 0; k < nk; ++k) {
        if (k + 1 < nk) GEMM_LOAD_CHUNK(k + 1);
        #pragma unroll
        for (int f = 0; f < 32; ++f) {
            const u64* wp = reinterpret_cast<const u64*>(&sW[f][ox * 16]);
            const u64* xp = reinterpret_cast<const u64*>(&sX[f][pxg * 4]);
            u64 w2r[8], x2r[2];
            #pragma unroll
            for (int i = 0; i < 8; ++i) w2r[i] = wp[i];
            x2r[0] = xp[0]; x2r[1] = xp[1];
            #pragma unroll
            for (int i = 0; i < 8; ++i) {
                fma2(acc[i][0], w2r[i], x2r[0]);
                fma2(acc[i][1], w2r[i], x2r[1]);
            }
        }
        __syncthreads();
        if (k + 1 < nk) { GEMM_STORE_CHUNK(); __syncthreads(); }
    }

    #pragma unroll
    for (int i = 0; i < 8; ++i) {
        const int o = o0 + ox * 8 + i;
        if (o >= Cout) continue;
        const float bo_ = bias[o] + (bias2 ? bias2[o] : 0.f);
        float v0, v1, v2, v3;
        unpack2(v0, v1, acc[i][0]);
        unpack2(v2, v3, acc[i][1]);
        float4 r = {v0 + bo_, v1 + bo_, v2 + bo_, v3 + bo_};
        *reinterpret_cast<float4*>(&Out[(long)n * oStride + (long)o * HW + p0 + pxg * 4]) = r;
    }
}

// ============ GRN tail (f32x2): out = Xres + ga*sigmoid(gb), [ga;gb] = Wo*concat_elu(H)+bo ============
// Dynamic smem: sWa[32][136] | sWb[32][136] | sX[32][128]  = 51200 bytes
#define GRNF_SWA(f, c) dsm[(f) * 136 + (c)]
#define GRNF_SWB(f, c) dsm[4352 + (f) * 136 + (c)]
#define GRNF_SX(f, p)  dsm[8704 + (f) * 128 + (p)]
#define GRNF_SMEM_BYTES 51200

#define GRNF_LOAD_CHUNK(kk)                                                          \
    {                                                                                \
        const int  c0    = (kk) * 16;                                                \
        const int  cbase = c0 + (fw & 15);                                           \
        const int  wcol  = (fw < 16) ? cbase : (C + cbase);                          \
        const bool cok   = cbase < C;                                                \
        _Pragma("unroll")                                                            \
        for (int i = 0; i < 8; ++i) {                                                \
            const int o = o0 + o8 + i * 8;                                           \
            const bool ok = cok && o < C;                                            \
            wrega[i] = ok ? Wo[(long)o       * (2 * C) + wcol] : 0.f;                \
            wregb[i] = ok ? Wo[(long)(o + C) * (2 * C) + wcol] : 0.f;                \
        }                                                                            \
        _Pragma("unroll")                                                            \
        for (int i = 0; i < 8; ++i) {                                                \
            const int c = c0 + c2 + i * 2;                                           \
            xreg[i] = (c < C) ? Hn[(long)c * HW + p0 + px] : 0.f;                    \
        }                                                                            \
    }

#define GRNF_STORE_CHUNK()                                                           \
    {                                                                                \
        _Pragma("unroll")                                                            \
        for (int i = 0; i < 8; ++i) {                                                \
            float2 wa = {wrega[i], wrega[i]};                                        \
            float2 wb = {wregb[i], wregb[i]};                                        \
            *reinterpret_cast<float2*>(&GRNF_SWA(fw, (o8 + i * 8) * 2)) = wa;        \
            *reinterpret_cast<float2*>(&GRNF_SWB(fw, (o8 + i * 8) * 2)) = wb;        \
        }                                                                            \
        _Pragma("unroll")                                                            \
        for (int i = 0; i < 8; ++i) {                                                \
            const int   cl = c2 + i * 2;                                             \
            const float v  = xreg[i];                                                \
            GRNF_SX(cl, px)      = eluf(v);                                          \
            GRNF_SX(cl + 16, px) = eluf(-v);                                         \
        }                                                                            \
    }

__global__ void __launch_bounds__(256)
grn_final_kernel(const float* __restrict__ H, long hStride, int C,
                 const float* __restrict__ Wo, const float* __restrict__ bo,
                 const float* __restrict__ Xres, long xStride,
                 float* __restrict__ Out, long oStride) {
    extern __shared__ __align__(16) float dsm[];
    const int tid = threadIdx.x;
    const int n  = blockIdx.y >> 3;
    const int p0 = (blockIdx.y & 7) * 128;
    const int o0 = blockIdx.x * 64;
    const float* Hn = H + (long)n * hStride;

    const int fw  = tid & 31;
    const int o8  = tid >> 5;
    const int px  = tid & 127;
    const int c2  = tid >> 7;
    const int ox  = tid & 7;
    const int pxg = tid >> 3;

    const int nk = (C + 15) >> 4;
    float wrega[8], wregb[8], xreg[8];
    u64 acca[8][2], accb[8][2];
    #pragma unroll
    for (int i = 0; i < 8; ++i) {
        acca[i][0] = acca[i][1] = 0ull;
        accb[i][0] = accb[i][1] = 0ull;
    }

    GRNF_LOAD_CHUNK(0);
    GRNF_STORE_CHUNK();
    __syncthreads();

    for (int k = 0; k < nk; ++k) {
        if (k + 1 < nk) GRNF_LOAD_CHUNK(k + 1);
        #pragma unroll
        for (int f = 0; f < 32; ++f) {
            const u64* wpa = reinterpret_cast<const u64*>(&GRNF_SWA(f, ox * 16));
            const u64* wpb = reinterpret_cast<const u64*>(&GRNF_SWB(f, ox * 16));
            const u64* xp  = reinterpret_cast<const u64*>(&GRNF_SX(f, pxg * 4));
            u64 wa2[8], wb2[8], x2r[2];
            #pragma unroll
            for (int i = 0; i < 8; ++i) { wa2[i] = wpa[i]; wb2[i] = wpb[i]; }
            x2r[0] = xp[0]; x2r[1] = xp[1];
            #pragma unroll
            for (int i = 0; i < 8; ++i) {
                fma2(acca[i][0], wa2[i], x2r[0]);
                fma2(acca[i][1], wa2[i], x2r[1]);
                fma2(accb[i][0], wb2[i], x2r[0]);
                fma2(accb[i][1], wb2[i], x2r[1]);
            }
        }
        __syncthreads();
        if (k + 1 < nk) { GRNF_STORE_CHUNK(); __syncthreads(); }
    }

    #pragma unroll
    for (int i = 0; i < 8; ++i) {
        const int o = o0 + ox * 8 + i;
        if (o >= C) continue;
        const float ba = bo[o];
        const float bb = bo[o + C];
        const float4 xr4 = *reinterpret_cast<const float4*>(
            &Xres[(long)n * xStride + (long)o * HW + p0 + pxg * 4]);
        const float xres[4] = {xr4.x, xr4.y, xr4.z, xr4.w};
        float gav[4], gbv[4];
        unpack2(gav[0], gav[1], acca[i][0]);
        unpack2(gav[2], gav[3], acca[i][1]);
        unpack2(gbv[0], gbv[1], accb[i][0]);
        unpack2(gbv[2], gbv[3], accb[i][1]);
        float rv[4];
        #pragma unroll
        for (int j = 0; j < 4; ++j) {
            const float ga = gav[j] + ba;
            const float gb = gbv[j] + bb;
            const float sig = 1.f / (1.f + expf(-gb));
            rv[j] = xres[j] + ga * sig;
        }
        float4 r = {rv[0], rv[1], rv[2], rv[3]};
        *reinterpret_cast<float4*>(&Out[(long)n * oStride + (long)o * HW + p0 + pxg * 4]) = r;
    }
}

// ---------------- small projection: Out[n, m0..m0+MT, hw] = W*X + b ----------------
template <int MT>
__global__ void __launch_bounds__(256)
proj_kernel(const float* __restrict__ X, int Cin,
            const float* __restrict__ W, const float* __restrict__ bias,
            float* __restrict__ Out, int M) {
    __shared__ float sW[MT * 176];
    const int n  = blockIdx.y;
    const int m0 = blockIdx.z * MT;
    const int p  = blockIdx.x * 256 + threadIdx.x;
    for (int i = threadIdx.x; i < MT * Cin; i += 256) {
        const int o = i / Cin, c = i - o * Cin;
        sW[o * 176 + c] = W[(long)(m0 + o) * Cin + c];
    }
    __syncthreads();
    const float* Xn = X + (long)n * Cin * HW;
    float acc[MT];
    #pragma unroll
    for (int o = 0; o < MT; ++o) acc[o] = 0.f;
    #pragma unroll 4
    for (int c = 0; c < Cin; ++c) {
        const float v = Xn[(long)c * HW + p];
        #pragma unroll
        for (int o = 0; o < MT; ++o) acc[o] = fmaf(sW[o * 176 + c], v, acc[o]);
    }
    #pragma unroll
    for (int o = 0; o < MT; ++o)
        Out[((long)n * M + m0 + o) * HW + p] = acc[o] + bias[m0 + o];
}

// ---------------- presoftmax: S[n,q,k] = sum_j K[n,j,k]*Q[n,j,q]  (lower tiles only) ----------------
__global__ void qk_kernel(const float* __restrict__ Kt, const float* __restrict__ Qt,
                          float* __restrict__ S) {
    const int n  = blockIdx.z;
    const int q0 = blockIdx.y * 64;
    const int k0 = blockIdx.x * 64;
    if (k0 > q0) return;
    __shared__ float sK[16][64];
    __shared__ float sQ[16][64];
    const float* Kn = Kt + (long)n * KDIM * HW;
    const float* Qn = Qt + (long)n * KDIM * HW;
    const int p  = threadIdx.x & 63;
    const int jr = threadIdx.x >> 6;
    #pragma unroll
    for (int pass = 0; pass < 4; ++pass) {
        const int j = jr + pass * 4;
        sK[j][p] = Kn[(long)j * HW + k0 + p];
        sQ[j][p] = Qn[(long)j * HW + q0 + p];
    }
    __syncthreads();
    const int tx = threadIdx.x & 15, ty = threadIdx.x >> 4;
    float acc[4][4] = {};
    #pragma unroll
    for (int j = 0; j < 16; ++j) {
        const float4 q4 = *reinterpret_cast<const float4*>(&sQ[j][ty * 4]);
        const float4 k4 = *reinterpret_cast<const float4*>(&sK[j][tx * 4]);
        const float qr[4] = {q4.x, q4.y, q4.z, q4.w};
        const float kr[4] = {k4.x, k4.y, k4.z, k4.w};
        #pragma unroll
        for (int i = 0; i < 4; ++i)
            #pragma unroll
            for (int jj = 0; jj < 4; ++jj)
                acc[i][jj] = fmaf(qr[i], kr[jj], acc[i][jj]);
    }
    float* Sn = S + (long)n * HW * HW;
    #pragma unroll
    for (int i = 0; i < 4; ++i) {
        float4 r = {acc[i][0], acc[i][1], acc[i][2], acc[i][3]};
        *reinterpret_cast<float4*>(&Sn[(long)(q0 + ty * 4 + i) * HW + k0 + tx * 4]) = r;
    }
}

// ---------------- causal softmax per row (faithful semantics) ----------------
__global__ void softmax_kernel(float* __restrict__ S) {
    const int q = blockIdx.x;
    const int n = blockIdx.y;
    float* row = S + ((long)n * HW + (long)q) * HW;
    const int tid = threadIdx.x;  // 256
    __shared__ float red[256];

    float vals[4];
    float lmax = 0.f;
    #pragma unroll
    for (int i = 0; i < 4; ++i) {
        const int k = tid + i * 256;
        const float s = (k < q) ? row[k] : 0.f;
        vals[i] = s;
        if (k < q) lmax = fmaxf(lmax, s);
    }
    red[tid] = lmax;
    __syncthreads();
    for (int s2 = 128; s2 > 0; s2 >>= 1) {
        if (tid < s2) red[tid] = fmaxf(red[tid], red[tid + s2]);
        __syncthreads();
    }
    const float m = red[0];
    __syncthreads();

    float e[4];
    float lsum = 0.f;
    #pragma unroll
    for (int i = 0; i < 4; ++i) {
        const int k = tid + i * 256;
        e[i] = (k < q) ? expf(vals[i] - m) : 0.f;
        lsum += e[i];
    }
    red[tid] = lsum;
    __syncthreads();
    for (int s2 = 128; s2 > 0; s2 >>= 1) {
        if (tid < s2) red[tid] += red[tid + s2];
        __syncthreads();
    }
    const float Skept = red[0];
    const float D = Skept + (float)(HW - q) * expf(-m);
    const float inv = 1.f / (Skept + 1e-7f * D);
    const int kmax = (q & ~63) + 64;   // av only consumes k < roundup(q+1, 64)
    #pragma unroll
    for (int i = 0; i < 4; ++i) {
        const int k = tid + i * 256;
        if (k < kmax) row[k] = e[i] * inv;
    }
}

// ---------------- AV: Out[n,v,q] = sum_j Att[n,q,j] * V[n,v,j]  (K causally truncated) ----------------
__global__ void av_kernel(const float* __restrict__ Att, const float* __restrict__ V,
                          float* __restrict__ Out) {
    __shared__ float sV[16][80];
    __shared__ float sW[16][64];
    const int n  = blockIdx.y;
    const int q0 = blockIdx.x * 64;
    const float* An = Att + (long)n * HW * HW;
    const float* Vn = V + (long)n * VDIM * HW;
    const int tx = threadIdx.x & 15, ty = threadIdx.x >> 4;
    float acc[5][4] = {};
    const int jmax = min(HW, q0 + 64);

    for (int j0 = 0; j0 < jmax; j0 += 16) {
        for (int i = threadIdx.x; i < 16 * 80; i += 256) {
            const int v = i >> 4, jj = i & 15;
            sV[jj][v] = Vn[(long)v * HW + j0 + jj];
        }
        for (int i = threadIdx.x; i < 16 * 64; i += 256) {
            const int qq = i >> 4, jj = i & 15;
            sW[jj][qq] = An[(long)(q0 + qq) * HW + j0 + jj];
        }
        __syncthreads();
        #pragma unroll
        for (int jj = 0; jj < 16; ++jj) {
            const float4 w4 = *reinterpret_cast<const float4*>(&sW[jj][tx * 4]);
            const float wv[4] = {w4.x, w4.y, w4.z, w4.w};
            #pragma unroll
            for (int i = 0; i < 5; ++i) {
                const float vv = sV[jj][ty * 5 + i];
                #pragma unroll
                for (int j = 0; j < 4; ++j)
                    acc[i][j] = fmaf(vv, wv[j], acc[i][j]);
            }
        }
        __syncthreads();
    }
    #pragma unroll
    for (int i = 0; i < 5; ++i) {
        float4 r = {acc[i][0], acc[i][1], acc[i][2], acc[i][3]};
        *reinterpret_cast<float4*>(&Out[((long)n * VDIM + ty * 5 + i) * HW + q0 + tx * 4]) = r;
    }
}

// ---------------- launcher ----------------
extern "C" void kernel_launch(void* const* d_in, const int* in_sizes, int n_in,
                              void* d_out, int out_size) {
    (void)in_sizes; (void)n_in; (void)out_size;
    const float* x    = (const float*)d_in[0];
    const float* ul   = (const float*)d_in[1];
    const float* b    = (const float*)d_in[2];
    const float* gkWi = (const float*)d_in[3];
    const float* gkbi = (const float*)d_in[4];
    const float* gkWo = (const float*)d_in[5];
    const float* gkbo = (const float*)d_in[6];
    const float* gqWi = (const float*)d_in[7];
    const float* gqbi = (const float*)d_in[8];
    const float* gqWo = (const float*)d_in[9];
    const float* gqbo = (const float*)d_in[10];
    const float* gvWi = (const float*)d_in[11];
    const float* gvbi = (const float*)d_in[12];
    const float* gvWo = (const float*)d_in[13];
    const float* gvbo = (const float*)d_in[14];
    const float* nkW  = (const float*)d_in[15];
    const float* nkb  = (const float*)d_in[16];
    const float* nqW  = (const float*)d_in[17];
    const float* nqb  = (const float*)d_in[18];
    const float* nvW  = (const float*)d_in[19];
    const float* nvb  = (const float*)d_in[20];
    const float* goWi = (const float*)d_in[21];
    const float* gobi = (const float*)d_in[22];
    const float* goWs = (const float*)d_in[23];
    const float* gobs = (const float*)d_in[24];
    const float* goWo = (const float*)d_in[25];
    const float* gobo = (const float*)d_in[26];
    float* out = (float*)d_out;

    float *p_cat, *p_h, *p_gout, *p_keys, *p_quer, *p_vals, *p_att, *p_attv;
    cudaGetSymbolAddress((void**)&p_cat,  g_cat);
    cudaGetSymbolAddress((void**)&p_h,    g_h);
    cudaGetSymbolAddress((void**)&p_gout, g_gout);
    cudaGetSymbolAddress((void**)&p_keys, g_keys);
    cudaGetSymbolAddress((void**)&p_quer, g_quer);
    cudaGetSymbolAddress((void**)&p_vals, g_vals);
    cudaGetSymbolAddress((void**)&p_att,  g_att);
    cudaGetSymbolAddress((void**)&p_attv, g_attv);

    cudaFuncSetAttribute(grn_final_kernel,
                         cudaFuncAttributeMaxDynamicSharedMemorySize, GRNF_SMEM_BYTES);

    const long sCat = (long)CKC * HW;
    const long sQ   = (long)CQC * HW;
    const long sO   = (long)COC * HW;
    const long sV   = (long)VDIM * HW;

    {
        const long total = (long)NB * CKC * HW;
        build_cat_kernel<<<(unsigned)((total + 255) / 256), 256>>>(x, ul, b, p_cat);
    }

    dim3 gridG(3, NB * 8);   // 3 out-tiles of 64 (Cout<=169), 8 px-tiles of 128

    // --- GRN-K -> keys ---
    gemm_celu_kernel<<<gridG, 256>>>(p_cat, sCat, CKC, gkWi,
                                     nullptr, 0, 0, nullptr, gkbi, nullptr,
                                     CKC, p_h, sCat);
    grn_final_kernel<<<gridG, 256, GRNF_SMEM_BYTES>>>(p_h, sCat, CKC, gkWo, gkbo,
                                                      p_cat, sCat, p_gout, sCat);
    proj_kernel<16><<<dim3(4, NB, 1), 256>>>(p_gout, CKC, nkW, nkb, p_keys, KDIM);

    // --- GRN-Q -> queries (ul_b is a channel-offset view of cat) ---
    gemm_celu_kernel<<<gridG, 256>>>(p_cat + 3 * HW, sCat, CQC, gqWi,
                                     nullptr, 0, 0, nullptr, gqbi, nullptr,
                                     CQC, p_h, sQ);
    grn_final_kernel<<<gridG, 256, GRNF_SMEM_BYTES>>>(p_h, sQ, CQC, gqWo, gqbo,
                                                      p_cat + 3 * HW, sCat, p_gout, sQ);
    proj_kernel<16><<<dim3(4, NB, 1), 256>>>(p_gout, CQC, nqW, nqb, p_quer, KDIM);

    // --- GRN-V -> values ---
    gemm_celu_kernel<<<gridG, 256>>>(p_cat, sCat, CKC, gvWi,
                                     nullptr, 0, 0, nullptr, gvbi, nullptr,
                                     CKC, p_h, sCat);
    grn_final_kernel<<<gridG, 256, GRNF_SMEM_BYTES>>>(p_h, sCat, CKC, gvWo, gvbo,
                                                      p_cat, sCat, p_gout, sCat);
    proj_kernel<16><<<dim3(4, NB, 5), 256>>>(p_gout, CKC, nvW, nvb, p_vals, VDIM);

    // --- attention ---
    qk_kernel<<<dim3(16, 16, NB), 256>>>(p_keys, p_quer, p_att);
    softmax_kernel<<<dim3(HW, NB), 256>>>(p_att);
    av_kernel<<<dim3(16, NB), 256>>>(p_att, p_vals, p_attv);

    // --- GRN-O (aux = att_v), dual-input fused GEMM -> output ---
    gemm_celu_kernel<<<gridG, 256>>>(ul, sO, COC, goWi,
                                     p_attv, sV, VDIM, goWs, gobi, gobs,
                                     COC, p_h, sO);
    grn_final_kernel<<<gridG, 256, GRNF_SMEM_BYTES>>>(p_h, sO, COC, goWo, gobo,
                                                      ul, sO, out, sO);
}

// round 7
// speedup vs baseline: 3.9963x; 3.9963x over previous
#include <cuda_runtime.h>
#include <cuda_fp16.h>
#include <math.h>
#include <stdint.h>

#define NB 32
#define HW 1024

#define CKC 169   // x_ul_b channels
#define CQC 166   // ul_b channels
#define COC 160   // ul channels
#define KDIM 16
#define VDIM 80

// ---------------- scratch (static device memory; no allocations) ----------------
__device__ float g_cat [(size_t)NB * CKC * HW];       // x_ul_b [n,169,1024]; ul_b = view +3*HW
__device__ float g_h   [(size_t)NB * CKC * HW];       // GRN hidden
__device__ float g_big [(size_t)NB * 2 * CKC * HW];   // GRN stage-2 raw [2C, hw]
__device__ float g_gout[(size_t)NB * CKC * HW];       // GRN output
__device__ float g_keys[(size_t)NB * KDIM * HW];
__device__ float g_quer[(size_t)NB * KDIM * HW];
__device__ float g_vals[(size_t)NB * VDIM * HW];
__device__ float g_att [(size_t)NB * HW * HW];
__device__ float g_attv[(size_t)NB * VDIM * HW];

__device__ __forceinline__ float eluf(float v) { return v > 0.f ? v : (expf(v) - 1.f); }

__device__ __forceinline__ void mma_f16(float* d, const unsigned* a, const unsigned* b) {
    asm volatile(
        "mma.sync.aligned.m16n8k16.row.col.f32.f16.f16.f32 "
        "{%0,%1,%2,%3}, {%4,%5,%6,%7}, {%8,%9}, {%0,%1,%2,%3};"
        : "+f"(d[0]), "+f"(d[1]), "+f"(d[2]), "+f"(d[3])
        : "r"(a[0]), "r"(a[1]), "r"(a[2]), "r"(a[3]), "r"(b[0]), "r"(b[1]));
}

// ---------------- concat inputs into [n,169,hw] ----------------
__global__ void build_cat_kernel(const float* __restrict__ x, const float* __restrict__ ul,
                                 const float* __restrict__ b, float* __restrict__ cat) {
    long idx = (long)blockIdx.x * blockDim.x + threadIdx.x;
    const long total = (long)NB * CKC * HW;
    if (idx >= total) return;
    int p = (int)(idx % HW);
    int c = (int)((idx / HW) % CKC);
    int n = (int)(idx / ((long)CKC * HW));
    float v;
    if (c < 3)        v = x [((long)n * 3   + c        ) * HW + p];
    else if (c < 163) v = ul[((long)n * 160 + (c - 3)  ) * HW + p];
    else              v = b [((long)n * 6   + (c - 163)) * HW + p];
    cat[idx] = v;
}

// ============ FP16 MMA GEMM: Out = W*concat_elu(X) [+ W2*concat_elu(X2)] + bias[+bias2] ============
// Block tile: 64 out x 128 px, 256 threads = 8 warps, each warp 64(out) x 16(px).
// K chunks of 32 features (2 k16 steps). A = W (fp16), B = concat_elu(X) (fp16), fp32 accum.
// smem: sA [64][40] halves (row-major out x feat), sB [128][44] halves (px x feat).

#define SA_STRIDE 40
#define SB_STRIDE 44

#define MG_LOAD_CHUNK(kk)                                                              \
    {                                                                                  \
        const float* Xs; const float* Ws; int Ci; long xs; int fb;                     \
        if ((kk) < nk1) { Xs = X;  Ws = W;  Ci = Cin;  xs = xStride;  fb = (kk) * 32; } \
        else            { Xs = X2; Ws = W2; Ci = Cin2; xs = x2Stride; fb = ((kk) - nk1) * 32; } \
        const int lim = 2 * Ci;                                                        \
        const int o = o0 + ao;                                                         \
        _Pragma("unroll")                                                              \
        for (int j = 0; j < 8; ++j) {                                                  \
            const int f = fb + afs + j;                                                \
            areg[j] = (o < Cout && f < lim) ? Ws[(long)o * lim + f] : 0.f;             \
        }                                                                              \
        const float* Xn = Xs + (long)n * xs;                                           \
        _Pragma("unroll")                                                              \
        for (int j = 0; j < 16; ++j) {                                                 \
            const int ff = fb + bf0 + j;                                               \
            float v = 0.f;                                                             \
            if (ff < lim) {                                                            \
                const int c  = (ff < Ci) ? ff : (ff - Ci);                             \
                const float xv = Xn[(long)c * HW + p0 + bp];                           \
                v = (ff < Ci) ? eluf(xv) : eluf(-xv);                                  \
            }                                                                          \
            breg[j] = v;                                                               \
        }                                                                              \
    }

#define MG_STORE_CHUNK()                                                               \
    {                                                                                  \
        _Pragma("unroll")                                                              \
        for (int jj = 0; jj < 4; ++jj)                                                 \
            *reinterpret_cast<__half2*>(&sA[ao * SA_STRIDE + afs + 2 * jj]) =          \
                __floats2half2_rn(areg[2 * jj], areg[2 * jj + 1]);                     \
        _Pragma("unroll")                                                              \
        for (int jj = 0; jj < 8; ++jj)                                                 \
            *reinterpret_cast<__half2*>(&sB[bp * SB_STRIDE + bf0 + 2 * jj]) =          \
                __floats2half2_rn(breg[2 * jj], breg[2 * jj + 1]);                     \
    }

__global__ void __launch_bounds__(256)
mma_gemm_celu(const float* __restrict__ X, long xStride, int Cin,
              const float* __restrict__ W,
              const float* __restrict__ X2, long x2Stride, int Cin2,
              const float* __restrict__ W2,
              const float* __restrict__ bias, const float* __restrict__ bias2,
              int Cout, float* __restrict__ Out, long oStride) {
    __shared__ __align__(16) __half sA[64 * SA_STRIDE];
    __shared__ __align__(16) __half sB[128 * SB_STRIDE];
    const int tid  = threadIdx.x;
    const int warp = tid >> 5;
    const int lane = tid & 31;
    const int n  = blockIdx.y >> 3;
    const int p0 = (blockIdx.y & 7) * 128;
    const int o0 = blockIdx.x * 64;

    // loader indices
    const int ao  = tid >> 2;          // A: out row (0..63)
    const int afs = (tid & 3) * 8;     // A: feature segment (8 feats)
    const int bp  = tid & 127;         // B: pixel
    const int bf0 = (tid >> 7) * 16;   // B: feature group (16 feats)
    // compute indices
    const int px0 = warp * 16;
    const int lq  = lane >> 2;         // 0..7
    const int lr  = lane & 3;          // 0..3

    const int nk1 = (2 * Cin + 31) >> 5;
    const int nk2 = W2 ? ((2 * Cin2 + 31) >> 5) : 0;
    const int nk  = nk1 + nk2;

    float areg[8], breg[16];
    float acc[4][2][4];
    #pragma unroll
    for (int m = 0; m < 4; ++m)
        #pragma unroll
        for (int nn = 0; nn < 2; ++nn)
            #pragma unroll
            for (int e = 0; e < 4; ++e) acc[m][nn][e] = 0.f;

    MG_LOAD_CHUNK(0);
    MG_STORE_CHUNK();
    __syncthreads();

    for (int k = 0; k < nk; ++k) {
        if (k + 1 < nk) MG_LOAD_CHUNK(k + 1);
        #pragma unroll
        for (int ks = 0; ks < 2; ++ks) {
            const int kb = ks * 16 + lr * 2;
            unsigned a[4][4], b[2][2];
            #pragma unroll
            for (int m = 0; m < 4; ++m) {
                const int r0 = m * 16 + lq;
                a[m][0] = *reinterpret_cast<const unsigned*>(&sA[r0 * SA_STRIDE + kb]);
                a[m][1] = *reinterpret_cast<const unsigned*>(&sA[(r0 + 8) * SA_STRIDE + kb]);
                a[m][2] = *reinterpret_cast<const unsigned*>(&sA[r0 * SA_STRIDE + kb + 8]);
                a[m][3] = *reinterpret_cast<const unsigned*>(&sA[(r0 + 8) * SA_STRIDE + kb + 8]);
            }
            #pragma unroll
            for (int nn = 0; nn < 2; ++nn) {
                const int pc = px0 + nn * 8 + lq;
                b[nn][0] = *reinterpret_cast<const unsigned*>(&sB[pc * SB_STRIDE + kb]);
                b[nn][1] = *reinterpret_cast<const unsigned*>(&sB[pc * SB_STRIDE + kb + 8]);
            }
            #pragma unroll
            for (int m = 0; m < 4; ++m)
                #pragma unroll
                for (int nn = 0; nn < 2; ++nn)
                    mma_f16(acc[m][nn], a[m], b[nn]);
        }
        __syncthreads();
        if (k + 1 < nk) { MG_STORE_CHUNK(); __syncthreads(); }
    }

    // epilogue
    #pragma unroll
    for (int m = 0; m < 4; ++m) {
        const int oa = o0 + m * 16 + lq;
        const int ob = oa + 8;
        const float ba = (oa < Cout) ? (bias[oa] + (bias2 ? bias2[oa] : 0.f)) : 0.f;
        const float bb = (ob < Cout) ? (bias[ob] + (bias2 ? bias2[ob] : 0.f)) : 0.f;
        #pragma unroll
        for (int nn = 0; nn < 2; ++nn) {
            const int pp = p0 + px0 + nn * 8 + 2 * lr;
            if (oa < Cout) {
                float2 r = {acc[m][nn][0] + ba, acc[m][nn][1] + ba};
                *reinterpret_cast<float2*>(&Out[(long)n * oStride + (long)oa * HW + pp]) = r;
            }
            if (ob < Cout) {
                float2 r = {acc[m][nn][2] + bb, acc[m][nn][3] + bb};
                *reinterpret_cast<float2*>(&Out[(long)n * oStride + (long)ob * HW + pp]) = r;
            }
        }
    }
}

// ---------------- gate: out = Xres + ga*sigmoid(gb), ga=G[c], gb=G[c+C] ----------------
__global__ void __launch_bounds__(256)
gate_kernel(const float* __restrict__ G, long gStride, int C,
            const float* __restrict__ Xres, long xStride,
            float* __restrict__ Out, long oStride, long total4) {
    long idx = (long)blockIdx.x * blockDim.x + threadIdx.x;
    if (idx >= total4) return;
    const int perImg = C * (HW / 4);
    const int n = (int)(idx / perImg);
    const int r = (int)(idx - (long)n * perImg);
    const int c = r / (HW / 4);
    const int p4 = (r - c * (HW / 4)) * 4;
    const float4 ga = *reinterpret_cast<const float4*>(&G[(long)n * gStride + (long)c * HW + p4]);
    const float4 gb = *reinterpret_cast<const float4*>(&G[(long)n * gStride + (long)(c + C) * HW + p4]);
    const float4 xr = *reinterpret_cast<const float4*>(&Xres[(long)n * xStride + (long)c * HW + p4]);
    float4 o;
    o.x = xr.x + ga.x / (1.f + expf(-gb.x));
    o.y = xr.y + ga.y / (1.f + expf(-gb.y));
    o.z = xr.z + ga.z / (1.f + expf(-gb.z));
    o.w = xr.w + ga.w / (1.f + expf(-gb.w));
    *reinterpret_cast<float4*>(&Out[(long)n * oStride + (long)c * HW + p4]) = o;
}

// ---------------- small projection: Out[n, m0..m0+MT, hw] = W*X + b ----------------
template <int MT>
__global__ void __launch_bounds__(256)
proj_kernel(const float* __restrict__ X, int Cin,
            const float* __restrict__ W, const float* __restrict__ bias,
            float* __restrict__ Out, int M) {
    __shared__ float sW[MT * 176];
    const int n  = blockIdx.y;
    const int m0 = blockIdx.z * MT;
    const int p  = blockIdx.x * 256 + threadIdx.x;
    for (int i = threadIdx.x; i < MT * Cin; i += 256) {
        const int o = i / Cin, c = i - o * Cin;
        sW[o * 176 + c] = W[(long)(m0 + o) * Cin + c];
    }
    __syncthreads();
    const float* Xn = X + (long)n * Cin * HW;
    float acc[MT];
    #pragma unroll
    for (int o = 0; o < MT; ++o) acc[o] = 0.f;
    #pragma unroll 4
    for (int c = 0; c < Cin; ++c) {
        const float v = Xn[(long)c * HW + p];
        #pragma unroll
        for (int o = 0; o < MT; ++o) acc[o] = fmaf(sW[o * 176 + c], v, acc[o]);
    }
    #pragma unroll
    for (int o = 0; o < MT; ++o)
        Out[((long)n * M + m0 + o) * HW + p] = acc[o] + bias[m0 + o];
}

// ---------------- presoftmax: S[n,q,k] = sum_j K[n,j,k]*Q[n,j,q]  (lower tiles only) ----------------
__global__ void qk_kernel(const float* __restrict__ Kt, const float* __restrict__ Qt,
                          float* __restrict__ S) {
    const int n  = blockIdx.z;
    const int q0 = blockIdx.y * 64;
    const int k0 = blockIdx.x * 64;
    if (k0 > q0) return;
    __shared__ float sK[16][64];
    __shared__ float sQ[16][64];
    const float* Kn = Kt + (long)n * KDIM * HW;
    const float* Qn = Qt + (long)n * KDIM * HW;
    const int p  = threadIdx.x & 63;
    const int jr = threadIdx.x >> 6;
    #pragma unroll
    for (int pass = 0; pass < 4; ++pass) {
        const int j = jr + pass * 4;
        sK[j][p] = Kn[(long)j * HW + k0 + p];
        sQ[j][p] = Qn[(long)j * HW + q0 + p];
    }
    __syncthreads();
    const int tx = threadIdx.x & 15, ty = threadIdx.x >> 4;
    float acc[4][4] = {};
    #pragma unroll
    for (int j = 0; j < 16; ++j) {
        const float4 q4 = *reinterpret_cast<const float4*>(&sQ[j][ty * 4]);
        const float4 k4 = *reinterpret_cast<const float4*>(&sK[j][tx * 4]);
        const float qr[4] = {q4.x, q4.y, q4.z, q4.w};
        const float kr[4] = {k4.x, k4.y, k4.z, k4.w};
        #pragma unroll
        for (int i = 0; i < 4; ++i)
            #pragma unroll
            for (int jj = 0; jj < 4; ++jj)
                acc[i][jj] = fmaf(qr[i], kr[jj], acc[i][jj]);
    }
    float* Sn = S + (long)n * HW * HW;
    #pragma unroll
    for (int i = 0; i < 4; ++i) {
        float4 r = {acc[i][0], acc[i][1], acc[i][2], acc[i][3]};
        *reinterpret_cast<float4*>(&Sn[(long)(q0 + ty * 4 + i) * HW + k0 + tx * 4]) = r;
    }
}

// ---------------- causal softmax per row (faithful semantics) ----------------
__global__ void softmax_kernel(float* __restrict__ S) {
    const int q = blockIdx.x;
    const int n = blockIdx.y;
    float* row = S + ((long)n * HW + (long)q) * HW;
    const int tid = threadIdx.x;  // 256
    __shared__ float red[256];

    float vals[4];
    float lmax = 0.f;
    #pragma unroll
    for (int i = 0; i < 4; ++i) {
        const int k = tid + i * 256;
        const float s = (k < q) ? row[k] : 0.f;
        vals[i] = s;
        if (k < q) lmax = fmaxf(lmax, s);
    }
    red[tid] = lmax;
    __syncthreads();
    for (int s2 = 128; s2 > 0; s2 >>= 1) {
        if (tid < s2) red[tid] = fmaxf(red[tid], red[tid + s2]);
        __syncthreads();
    }
    const float m = red[0];
    __syncthreads();

    float e[4];
    float lsum = 0.f;
    #pragma unroll
    for (int i = 0; i < 4; ++i) {
        const int k = tid + i * 256;
        e[i] = (k < q) ? expf(vals[i] - m) : 0.f;
        lsum += e[i];
    }
    red[tid] = lsum;
    __syncthreads();
    for (int s2 = 128; s2 > 0; s2 >>= 1) {
        if (tid < s2) red[tid] += red[tid + s2];
        __syncthreads();
    }
    const float Skept = red[0];
    const float D = Skept + (float)(HW - q) * expf(-m);
    const float inv = 1.f / (Skept + 1e-7f * D);
    const int kmax = (q & ~63) + 64;   // av only consumes k < roundup(q+1, 64)
    #pragma unroll
    for (int i = 0; i < 4; ++i) {
        const int k = tid + i * 256;
        if (k < kmax) row[k] = e[i] * inv;
    }
}

// ---------------- AV: Out[n,v,q] = sum_j Att[n,q,j] * V[n,v,j]  (K causally truncated) ----------------
__global__ void av_kernel(const float* __restrict__ Att, const float* __restrict__ V,
                          float* __restrict__ Out) {
    __shared__ float sV[16][80];
    __shared__ float sW[16][64];
    const int n  = blockIdx.y;
    const int q0 = blockIdx.x * 64;
    const float* An = Att + (long)n * HW * HW;
    const float* Vn = V + (long)n * VDIM * HW;
    const int tx = threadIdx.x & 15, ty = threadIdx.x >> 4;
    float acc[5][4] = {};
    const int jmax = min(HW, q0 + 64);

    for (int j0 = 0; j0 < jmax; j0 += 16) {
        for (int i = threadIdx.x; i < 16 * 80; i += 256) {
            const int v = i >> 4, jj = i & 15;
            sV[jj][v] = Vn[(long)v * HW + j0 + jj];
        }
        for (int i = threadIdx.x; i < 16 * 64; i += 256) {
            const int qq = i >> 4, jj = i & 15;
            sW[jj][qq] = An[(long)(q0 + qq) * HW + j0 + jj];
        }
        __syncthreads();
        #pragma unroll
        for (int jj = 0; jj < 16; ++jj) {
            const float4 w4 = *reinterpret_cast<const float4*>(&sW[jj][tx * 4]);
            const float wv[4] = {w4.x, w4.y, w4.z, w4.w};
            #pragma unroll
            for (int i = 0; i < 5; ++i) {
                const float vv = sV[jj][ty * 5 + i];
                #pragma unroll
                for (int j = 0; j < 4; ++j)
                    acc[i][j] = fmaf(vv, wv[j], acc[i][j]);
            }
        }
        __syncthreads();
    }
    #pragma unroll
    for (int i = 0; i < 5; ++i) {
        float4 r = {acc[i][0], acc[i][1], acc[i][2], acc[i][3]};
        *reinterpret_cast<float4*>(&Out[((long)n * VDIM + ty * 5 + i) * HW + q0 + tx * 4]) = r;
    }
}

// ---------------- launcher ----------------
extern "C" void kernel_launch(void* const* d_in, const int* in_sizes, int n_in,
                              void* d_out, int out_size) {
    (void)in_sizes; (void)n_in; (void)out_size;
    const float* x    = (const float*)d_in[0];
    const float* ul   = (const float*)d_in[1];
    const float* b    = (const float*)d_in[2];
    const float* gkWi = (const float*)d_in[3];
    const float* gkbi = (const float*)d_in[4];
    const float* gkWo = (const float*)d_in[5];
    const float* gkbo = (const float*)d_in[6];
    const float* gqWi = (const float*)d_in[7];
    const float* gqbi = (const float*)d_in[8];
    const float* gqWo = (const float*)d_in[9];
    const float* gqbo = (const float*)d_in[10];
    const float* gvWi = (const float*)d_in[11];
    const float* gvbi = (const float*)d_in[12];
    const float* gvWo = (const float*)d_in[13];
    const float* gvbo = (const float*)d_in[14];
    const float* nkW  = (const float*)d_in[15];
    const float* nkb  = (const float*)d_in[16];
    const float* nqW  = (const float*)d_in[17];
    const float* nqb  = (const float*)d_in[18];
    const float* nvW  = (const float*)d_in[19];
    const float* nvb  = (const float*)d_in[20];
    const float* goWi = (const float*)d_in[21];
    const float* gobi = (const float*)d_in[22];
    const float* goWs = (const float*)d_in[23];
    const float* gobs = (const float*)d_in[24];
    const float* goWo = (const float*)d_in[25];
    const float* gobo = (const float*)d_in[26];
    float* out = (float*)d_out;

    float *p_cat, *p_h, *p_big, *p_gout, *p_keys, *p_quer, *p_vals, *p_att, *p_attv;
    cudaGetSymbolAddress((void**)&p_cat,  g_cat);
    cudaGetSymbolAddress((void**)&p_h,    g_h);
    cudaGetSymbolAddress((void**)&p_big,  g_big);
    cudaGetSymbolAddress((void**)&p_gout, g_gout);
    cudaGetSymbolAddress((void**)&p_keys, g_keys);
    cudaGetSymbolAddress((void**)&p_quer, g_quer);
    cudaGetSymbolAddress((void**)&p_vals, g_vals);
    cudaGetSymbolAddress((void**)&p_att,  g_att);
    cudaGetSymbolAddress((void**)&p_attv, g_attv);

    const long sCat = (long)CKC * HW;
    const long sQ   = (long)CQC * HW;
    const long sO   = (long)COC * HW;
    const long sV   = (long)VDIM * HW;
    const long sBig = (long)2 * CKC * HW;

    {
        const long total = (long)NB * CKC * HW;
        build_cat_kernel<<<(unsigned)((total + 255) / 256), 256>>>(x, ul, b, p_cat);
    }

    const dim3 gridS1(3, NB * 8);    // Cout<=169 -> 3 out-tiles of 64
    const dim3 gridS2K(6, NB * 8);   // Cout=338 -> 6
    const dim3 gridS2Q(6, NB * 8);   // Cout=332 -> 6
    const dim3 gridS2O(5, NB * 8);   // Cout=320 -> 5

    // ---- GRN-K -> keys ----
    mma_gemm_celu<<<gridS1, 256>>>(p_cat, sCat, CKC, gkWi, nullptr, 0, 0, nullptr,
                                   gkbi, nullptr, CKC, p_h, sCat);
    mma_gemm_celu<<<gridS2K, 256>>>(p_h, sCat, CKC, gkWo, nullptr, 0, 0, nullptr,
                                    gkbo, nullptr, 2 * CKC, p_big, sBig);
    {
        const long t4 = (long)NB * CKC * (HW / 4);
        gate_kernel<<<(unsigned)((t4 + 255) / 256), 256>>>(p_big, sBig, CKC, p_cat, sCat, p_gout, sCat, t4);
    }
    proj_kernel<16><<<dim3(4, NB, 1), 256>>>(p_gout, CKC, nkW, nkb, p_keys, KDIM);

    // ---- GRN-Q -> queries (ul_b is a channel-offset view of cat) ----
    mma_gemm_celu<<<gridS1, 256>>>(p_cat + 3 * HW, sCat, CQC, gqWi, nullptr, 0, 0, nullptr,
                                   gqbi, nullptr, CQC, p_h, sQ);
    mma_gemm_celu<<<gridS2Q, 256>>>(p_h, sQ, CQC, gqWo, nullptr, 0, 0, nullptr,
                                    gqbo, nullptr, 2 * CQC, p_big, sBig);
    {
        const long t4 = (long)NB * CQC * (HW / 4);
        gate_kernel<<<(unsigned)((t4 + 255) / 256), 256>>>(p_big, sBig, CQC, p_cat + 3 * HW, sCat, p_gout, sQ, t4);
    }
    proj_kernel<16><<<dim3(4, NB, 1), 256>>>(p_gout, CQC, nqW, nqb, p_quer, KDIM);

    // ---- GRN-V -> values ----
    mma_gemm_celu<<<gridS1, 256>>>(p_cat, sCat, CKC, gvWi, nullptr, 0, 0, nullptr,
                                   gvbi, nullptr, CKC, p_h, sCat);
    mma_gemm_celu<<<gridS2K, 256>>>(p_h, sCat, CKC, gvWo, nullptr, 0, 0, nullptr,
                                    gvbo, nullptr, 2 * CKC, p_big, sBig);
    {
        const long t4 = (long)NB * CKC * (HW / 4);
        gate_kernel<<<(unsigned)((t4 + 255) / 256), 256>>>(p_big, sBig, CKC, p_cat, sCat, p_gout, sCat, t4);
    }
    proj_kernel<16><<<dim3(4, NB, 5), 256>>>(p_gout, CKC, nvW, nvb, p_vals, VDIM);

    // ---- attention ----
    qk_kernel<<<dim3(16, 16, NB), 256>>>(p_keys, p_quer, p_att);
    softmax_kernel<<<dim3(HW, NB), 256>>>(p_att);
    av_kernel<<<dim3(16, NB), 256>>>(p_att, p_vals, p_attv);

    // ---- GRN-O (aux = att_v), dual-input fused stage-1 ----
    mma_gemm_celu<<<gridS1, 256>>>(ul, sO, COC, goWi, p_attv, sV, VDIM, goWs,
                                   gobi, gobs, COC, p_h, sO);
    mma_gemm_celu<<<gridS2O, 256>>>(p_h, sO, COC, goWo, nullptr, 0, 0, nullptr,
                                    gobo, nullptr, 2 * COC, p_big, sBig);
    {
        const long t4 = (long)NB * COC * (HW / 4);
        gate_kernel<<<(unsigned)((t4 + 255) / 256), 256>>>(p_big, sBig, COC, ul, sO, out, sO, t4);
    }
}

// round 8
// speedup vs baseline: 3.9982x; 1.0005x over previous
#include <cuda_runtime.h>
#include <cuda_fp16.h>
#include <math.h>
#include <stdint.h>

#define NB 32
#define HW 1024

#define CKC 169   // x_ul_b channels
#define CQC 166   // ul_b channels
#define COC 160   // ul channels
#define KDIM 16
#define VDIM 80

// ---------------- scratch (static device memory; no allocations) ----------------
__device__ float g_cat [(size_t)NB * CKC * HW];       // x_ul_b [n,169,1024]; ul_b = view +3*HW
__device__ float g_h   [(size_t)NB * CKC * HW];       // GRN hidden
__device__ float g_big [(size_t)NB * 2 * CKC * HW];   // GRN stage-2 raw [2C, hw]
__device__ float g_gout[(size_t)NB * CKC * HW];       // GRN output
__device__ float g_keys[(size_t)NB * KDIM * HW];
__device__ float g_quer[(size_t)NB * KDIM * HW];
__device__ float g_vals[(size_t)NB * VDIM * HW];
__device__ float g_att [(size_t)NB * HW * HW];
__device__ float g_attv[(size_t)NB * VDIM * HW];

__device__ __forceinline__ float eluf(float v) { return v > 0.f ? v : (expf(v) - 1.f); }

__device__ __forceinline__ void mma_f16(float* d, const unsigned* a, const unsigned* b) {
    asm volatile(
        "mma.sync.aligned.m16n8k16.row.col.f32.f16.f16.f32 "
        "{%0,%1,%2,%3}, {%4,%5,%6,%7}, {%8,%9}, {%0,%1,%2,%3};"
        : "+f"(d[0]), "+f"(d[1]), "+f"(d[2]), "+f"(d[3])
        : "r"(a[0]), "r"(a[1]), "r"(a[2]), "r"(a[3]), "r"(b[0]), "r"(b[1]));
}

// ---------------- concat inputs into [n,169,hw] ----------------
__global__ void build_cat_kernel(const float* __restrict__ x, const float* __restrict__ ul,
                                 const float* __restrict__ b, float* __restrict__ cat) {
    long idx = (long)blockIdx.x * blockDim.x + threadIdx.x;
    const long total = (long)NB * CKC * HW;
    if (idx >= total) return;
    int p = (int)(idx % HW);
    int c = (int)((idx / HW) % CKC);
    int n = (int)(idx / ((long)CKC * HW));
    float v;
    if (c < 3)        v = x [((long)n * 3   + c        ) * HW + p];
    else if (c < 163) v = ul[((long)n * 160 + (c - 3)  ) * HW + p];
    else              v = b [((long)n * 6   + (c - 163)) * HW + p];
    cat[idx] = v;
}

// ============ FP16 MMA GEMM: Out = W*concat_elu(X) [+ W2*concat_elu(X2)] + bias[+bias2] ============
// CTA tile: 64 out x 128 px, 256 threads = 8 warps (2 M-groups x 4 N-groups), warp tile 32x32.
// K chunks of 32 features, TWO smem buffer pairs, ONE sync per chunk (ping-pong).

#define SAH 34   // smem stride in halves (17 banks -> conflict-free B stores)

#define MG_LOAD_CHUNK(kk)                                                              \
    {                                                                                  \
        const float* Xs; const float* Ws; int Ci; long xs; int fb;                     \
        if ((kk) < nk1) { Xs = X;  Ws = W;  Ci = Cin;  xs = xStride;  fb = (kk) * 32; } \
        else            { Xs = X2; Ws = W2; Ci = Cin2; xs = x2Stride; fb = ((kk) - nk1) * 32; } \
        const int lim = 2 * Ci;                                                        \
        const int o = o0 + arow;                                                       \
        const bool oOK = o < Cout;                                                     \
        _Pragma("unroll")                                                              \
        for (int jj = 0; jj < 4; ++jj) {                                               \
            const int f = fb + afs + 2 * jj;                                           \
            float2 w2 = {0.f, 0.f};                                                    \
            if (oOK && f < lim)                                                        \
                w2 = *reinterpret_cast<const float2*>(&Ws[(long)o * lim + f]);         \
            areg[2 * jj] = w2.x; areg[2 * jj + 1] = w2.y;                              \
        }                                                                              \
        const float* Xn = Xs + (long)n * xs;                                           \
        _Pragma("unroll")                                                              \
        for (int j = 0; j < 16; ++j) {                                                 \
            const int ff = fb + bf0 + j;                                               \
            float v = 0.f;                                                             \
            if (ff < lim) {                                                            \
                const int c  = (ff < Ci) ? ff : (ff - Ci);                             \
                const float xv = Xn[(long)c * HW + p0 + bpx];                          \
                v = (ff < Ci) ? eluf(xv) : eluf(-xv);                                  \
            }                                                                          \
            breg[j] = v;                                                               \
        }                                                                              \
    }

#define MG_STORE_CHUNK(buf)                                                            \
    {                                                                                  \
        __half* pa = &sA[buf][arow * SAH + afs];                                       \
        _Pragma("unroll")                                                              \
        for (int jj = 0; jj < 4; ++jj)                                                 \
            *reinterpret_cast<__half2*>(pa + 2 * jj) =                                 \
                __floats2half2_rn(areg[2 * jj], areg[2 * jj + 1]);                     \
        __half* pb = &sB[buf][bpx * SAH + bf0];                                        \
        _Pragma("unroll")                                                              \
        for (int jj = 0; jj < 8; ++jj)                                                 \
            *reinterpret_cast<__half2*>(pb + 2 * jj) =                                 \
                __floats2half2_rn(breg[2 * jj], breg[2 * jj + 1]);                     \
    }

__global__ void __launch_bounds__(256)
mma_gemm_celu(const float* __restrict__ X, long xStride, int Cin,
              const float* __restrict__ W,
              const float* __restrict__ X2, long x2Stride, int Cin2,
              const float* __restrict__ W2,
              const float* __restrict__ bias, const float* __restrict__ bias2,
              int Cout, float* __restrict__ Out, long oStride) {
    __shared__ __align__(16) __half sA[2][64 * SAH];
    __shared__ __align__(16) __half sB[2][128 * SAH];
    const int tid  = threadIdx.x;
    const int warp = tid >> 5;
    const int lane = tid & 31;
    const int n  = blockIdx.y >> 3;
    const int p0 = (blockIdx.y & 7) * 128;
    const int o0 = blockIdx.x * 64;

    // loader indices
    const int arow = tid >> 2;          // A: out row (0..63)
    const int afs  = (tid & 3) * 8;     // A: feature offset (8 feats)
    const int bpx  = tid & 127;         // B: pixel
    const int bf0  = (tid >> 7) * 16;   // B: feature group (16 feats)
    // compute indices: 2 M-groups x 4 N-groups of 32x32
    const int m0w = (warp & 1) * 32;
    const int n0w = (warp >> 1) * 32;
    const int lq  = lane >> 2;          // 0..7
    const int lr  = lane & 3;           // 0..3

    const int nk1 = (2 * Cin + 31) >> 5;
    const int nk2 = W2 ? ((2 * Cin2 + 31) >> 5) : 0;
    const int nk  = nk1 + nk2;

    float areg[8], breg[16];
    float acc[2][4][4];
    #pragma unroll
    for (int mi = 0; mi < 2; ++mi)
        #pragma unroll
        for (int ni = 0; ni < 4; ++ni)
            #pragma unroll
            for (int e = 0; e < 4; ++e) acc[mi][ni][e] = 0.f;

    MG_LOAD_CHUNK(0);
    MG_STORE_CHUNK(0);
    __syncthreads();

    for (int k = 0; k < nk; ++k) {
        const int buf = k & 1;
        if (k + 1 < nk) MG_LOAD_CHUNK(k + 1);
        #pragma unroll
        for (int ks = 0; ks < 2; ++ks) {
            const int kb = ks * 16 + lr * 2;
            unsigned a[2][4], b[4][2];
            #pragma unroll
            for (int mi = 0; mi < 2; ++mi) {
                const __half* pa = &sA[buf][(m0w + mi * 16 + lq) * SAH + kb];
                a[mi][0] = *reinterpret_cast<const unsigned*>(pa);
                a[mi][1] = *reinterpret_cast<const unsigned*>(pa + 8 * SAH);
                a[mi][2] = *reinterpret_cast<const unsigned*>(pa + 8);
                a[mi][3] = *reinterpret_cast<const unsigned*>(pa + 8 * SAH + 8);
            }
            #pragma unroll
            for (int ni = 0; ni < 4; ++ni) {
                const __half* pb = &sB[buf][(n0w + ni * 8 + lq) * SAH + kb];
                b[ni][0] = *reinterpret_cast<const unsigned*>(pb);
                b[ni][1] = *reinterpret_cast<const unsigned*>(pb + 8);
            }
            #pragma unroll
            for (int mi = 0; mi < 2; ++mi)
                #pragma unroll
                for (int ni = 0; ni < 4; ++ni)
                    mma_f16(acc[mi][ni], a[mi], b[ni]);
        }
        if (k + 1 < nk) MG_STORE_CHUNK((k + 1) & 1);   // writes the idle buffer
        __syncthreads();
    }

    // epilogue
    #pragma unroll
    for (int mi = 0; mi < 2; ++mi) {
        const int oa = o0 + m0w + mi * 16 + lq;
        const int ob = oa + 8;
        const float ba = (oa < Cout) ? (bias[oa] + (bias2 ? bias2[oa] : 0.f)) : 0.f;
        const float bb = (ob < Cout) ? (bias[ob] + (bias2 ? bias2[ob] : 0.f)) : 0.f;
        #pragma unroll
        for (int ni = 0; ni < 4; ++ni) {
            const int pp = p0 + n0w + ni * 8 + 2 * lr;
            if (oa < Cout) {
                float2 r = {acc[mi][ni][0] + ba, acc[mi][ni][1] + ba};
                *reinterpret_cast<float2*>(&Out[(long)n * oStride + (long)oa * HW + pp]) = r;
            }
            if (ob < Cout) {
                float2 r = {acc[mi][ni][2] + bb, acc[mi][ni][3] + bb};
                *reinterpret_cast<float2*>(&Out[(long)n * oStride + (long)ob * HW + pp]) = r;
            }
        }
    }
}

// ---------------- gate: out = Xres + ga*sigmoid(gb), ga=G[c], gb=G[c+C] ----------------
__global__ void __launch_bounds__(256)
gate_kernel(const float* __restrict__ G, long gStride, int C,
            const float* __restrict__ Xres, long xStride,
            float* __restrict__ Out, long oStride, long total4) {
    long idx = (long)blockIdx.x * blockDim.x + threadIdx.x;
    if (idx >= total4) return;
    const int perImg = C * (HW / 4);
    const int n = (int)(idx / perImg);
    const int r = (int)(idx - (long)n * perImg);
    const int c = r / (HW / 4);
    const int p4 = (r - c * (HW / 4)) * 4;
    const float4 ga = *reinterpret_cast<const float4*>(&G[(long)n * gStride + (long)c * HW + p4]);
    const float4 gb = *reinterpret_cast<const float4*>(&G[(long)n * gStride + (long)(c + C) * HW + p4]);
    const float4 xr = *reinterpret_cast<const float4*>(&Xres[(long)n * xStride + (long)c * HW + p4]);
    float4 o;
    o.x = xr.x + ga.x / (1.f + expf(-gb.x));
    o.y = xr.y + ga.y / (1.f + expf(-gb.y));
    o.z = xr.z + ga.z / (1.f + expf(-gb.z));
    o.w = xr.w + ga.w / (1.f + expf(-gb.w));
    *reinterpret_cast<float4*>(&Out[(long)n * oStride + (long)c * HW + p4]) = o;
}

// ---------------- small projection: Out[n, m0..m0+MT, hw] = W*X + b ----------------
template <int MT>
__global__ void __launch_bounds__(256)
proj_kernel(const float* __restrict__ X, int Cin,
            const float* __restrict__ W, const float* __restrict__ bias,
            float* __restrict__ Out, int M) {
    __shared__ float sW[MT * 176];
    const int n  = blockIdx.y;
    const int m0 = blockIdx.z * MT;
    const int p  = blockIdx.x * 256 + threadIdx.x;
    for (int i = threadIdx.x; i < MT * Cin; i += 256) {
        const int o = i / Cin, c = i - o * Cin;
        sW[o * 176 + c] = W[(long)(m0 + o) * Cin + c];
    }
    __syncthreads();
    const float* Xn = X + (long)n * Cin * HW;
    float acc[MT];
    #pragma unroll
    for (int o = 0; o < MT; ++o) acc[o] = 0.f;
    #pragma unroll 4
    for (int c = 0; c < Cin; ++c) {
        const float v = Xn[(long)c * HW + p];
        #pragma unroll
        for (int o = 0; o < MT; ++o) acc[o] = fmaf(sW[o * 176 + c], v, acc[o]);
    }
    #pragma unroll
    for (int o = 0; o < MT; ++o)
        Out[((long)n * M + m0 + o) * HW + p] = acc[o] + bias[m0 + o];
}

// ---------------- presoftmax: S[n,q,k] = sum_j K[n,j,k]*Q[n,j,q]  (lower tiles only) ----------------
__global__ void qk_kernel(const float* __restrict__ Kt, const float* __restrict__ Qt,
                          float* __restrict__ S) {
    const int n  = blockIdx.z;
    const int q0 = blockIdx.y * 64;
    const int k0 = blockIdx.x * 64;
    if (k0 > q0) return;
    __shared__ float sK[16][64];
    __shared__ float sQ[16][64];
    const float* Kn = Kt + (long)n * KDIM * HW;
    const float* Qn = Qt + (long)n * KDIM * HW;
    const int p  = threadIdx.x & 63;
    const int jr = threadIdx.x >> 6;
    #pragma unroll
    for (int pass = 0; pass < 4; ++pass) {
        const int j = jr + pass * 4;
        sK[j][p] = Kn[(long)j * HW + k0 + p];
        sQ[j][p] = Qn[(long)j * HW + q0 + p];
    }
    __syncthreads();
    const int tx = threadIdx.x & 15, ty = threadIdx.x >> 4;
    float acc[4][4] = {};
    #pragma unroll
    for (int j = 0; j < 16; ++j) {
        const float4 q4 = *reinterpret_cast<const float4*>(&sQ[j][ty * 4]);
        const float4 k4 = *reinterpret_cast<const float4*>(&sK[j][tx * 4]);
        const float qr[4] = {q4.x, q4.y, q4.z, q4.w};
        const float kr[4] = {k4.x, k4.y, k4.z, k4.w};
        #pragma unroll
        for (int i = 0; i < 4; ++i)
            #pragma unroll
            for (int jj = 0; jj < 4; ++jj)
                acc[i][jj] = fmaf(qr[i], kr[jj], acc[i][jj]);
    }
    float* Sn = S + (long)n * HW * HW;
    #pragma unroll
    for (int i = 0; i < 4; ++i) {
        float4 r = {acc[i][0], acc[i][1], acc[i][2], acc[i][3]};
        *reinterpret_cast<float4*>(&Sn[(long)(q0 + ty * 4 + i) * HW + k0 + tx * 4]) = r;
    }
}

// ---------------- causal softmax per row (faithful semantics) ----------------
__global__ void softmax_kernel(float* __restrict__ S) {
    const int q = blockIdx.x;
    const int n = blockIdx.y;
    float* row = S + ((long)n * HW + (long)q) * HW;
    const int tid = threadIdx.x;  // 256
    __shared__ float red[256];

    float vals[4];
    float lmax = 0.f;
    #pragma unroll
    for (int i = 0; i < 4; ++i) {
        const int k = tid + i * 256;
        const float s = (k < q) ? row[k] : 0.f;
        vals[i] = s;
        if (k < q) lmax = fmaxf(lmax, s);
    }
    red[tid] = lmax;
    __syncthreads();
    for (int s2 = 128; s2 > 0; s2 >>= 1) {
        if (tid < s2) red[tid] = fmaxf(red[tid], red[tid + s2]);
        __syncthreads();
    }
    const float m = red[0];
    __syncthreads();

    float e[4];
    float lsum = 0.f;
    #pragma unroll
    for (int i = 0; i < 4; ++i) {
        const int k = tid + i * 256;
        e[i] = (k < q) ? expf(vals[i] - m) : 0.f;
        lsum += e[i];
    }
    red[tid] = lsum;
    __syncthreads();
    for (int s2 = 128; s2 > 0; s2 >>= 1) {
        if (tid < s2) red[tid] += red[tid + s2];
        __syncthreads();
    }
    const float Skept = red[0];
    const float D = Skept + (float)(HW - q) * expf(-m);
    const float inv = 1.f / (Skept + 1e-7f * D);
    const int kmax = (q & ~63) + 64;   // av only consumes k < roundup(q+1, 64)
    #pragma unroll
    for (int i = 0; i < 4; ++i) {
        const int k = tid + i * 256;
        if (k < kmax) row[k] = e[i] * inv;
    }
}

// ---------------- AV: Out[n,v,q] = sum_j Att[n,q,j] * V[n,v,j]  (K causally truncated) ----------------
__global__ void av_kernel(const float* __restrict__ Att, const float* __restrict__ V,
                          float* __restrict__ Out) {
    __shared__ float sV[16][80];
    __shared__ float sW[16][64];
    const int n  = blockIdx.y;
    const int q0 = blockIdx.x * 64;
    const float* An = Att + (long)n * HW * HW;
    const float* Vn = V + (long)n * VDIM * HW;
    const int tx = threadIdx.x & 15, ty = threadIdx.x >> 4;
    float acc[5][4] = {};
    const int jmax = min(HW, q0 + 64);

    for (int j0 = 0; j0 < jmax; j0 += 16) {
        for (int i = threadIdx.x; i < 16 * 80; i += 256) {
            const int v = i >> 4, jj = i & 15;
            sV[jj][v] = Vn[(long)v * HW + j0 + jj];
        }
        for (int i = threadIdx.x; i < 16 * 64; i += 256) {
            const int qq = i >> 4, jj = i & 15;
            sW[jj][qq] = An[(long)(q0 + qq) * HW + j0 + jj];
        }
        __syncthreads();
        #pragma unroll
        for (int jj = 0; jj < 16; ++jj) {
            const float4 w4 = *reinterpret_cast<const float4*>(&sW[jj][tx * 4]);
            const float wv[4] = {w4.x, w4.y, w4.z, w4.w};
            #pragma unroll
            for (int i = 0; i < 5; ++i) {
                const float vv = sV[jj][ty * 5 + i];
                #pragma unroll
                for (int j = 0; j < 4; ++j)
                    acc[i][j] = fmaf(vv, wv[j], acc[i][j]);
            }
        }
        __syncthreads();
    }
    #pragma unroll
    for (int i = 0; i < 5; ++i) {
        float4 r = {acc[i][0], acc[i][1], acc[i][2], acc[i][3]};
        *reinterpret_cast<float4*>(&Out[((long)n * VDIM + ty * 5 + i) * HW + q0 + tx * 4]) = r;
    }
}

// ---------------- launcher ----------------
extern "C" void kernel_launch(void* const* d_in, const int* in_sizes, int n_in,
                              void* d_out, int out_size) {
    (void)in_sizes; (void)n_in; (void)out_size;
    const float* x    = (const float*)d_in[0];
    const float* ul   = (const float*)d_in[1];
    const float* b    = (const float*)d_in[2];
    const float* gkWi = (const float*)d_in[3];
    const float* gkbi = (const float*)d_in[4];
    const float* gkWo = (const float*)d_in[5];
    const float* gkbo = (const float*)d_in[6];
    const float* gqWi = (const float*)d_in[7];
    const float* gqbi = (const float*)d_in[8];
    const float* gqWo = (const float*)d_in[9];
    const float* gqbo = (const float*)d_in[10];
    const float* gvWi = (const float*)d_in[11];
    const float* gvbi = (const float*)d_in[12];
    const float* gvWo = (const float*)d_in[13];
    const float* gvbo = (const float*)d_in[14];
    const float* nkW  = (const float*)d_in[15];
    const float* nkb  = (const float*)d_in[16];
    const float* nqW  = (const float*)d_in[17];
    const float* nqb  = (const float*)d_in[18];
    const float* nvW  = (const float*)d_in[19];
    const float* nvb  = (const float*)d_in[20];
    const float* goWi = (const float*)d_in[21];
    const float* gobi = (const float*)d_in[22];
    const float* goWs = (const float*)d_in[23];
    const float* gobs = (const float*)d_in[24];
    const float* goWo = (const float*)d_in[25];
    const float* gobo = (const float*)d_in[26];
    float* out = (float*)d_out;

    float *p_cat, *p_h, *p_big, *p_gout, *p_keys, *p_quer, *p_vals, *p_att, *p_attv;
    cudaGetSymbolAddress((void**)&p_cat,  g_cat);
    cudaGetSymbolAddress((void**)&p_h,    g_h);
    cudaGetSymbolAddress((void**)&p_big,  g_big);
    cudaGetSymbolAddress((void**)&p_gout, g_gout);
    cudaGetSymbolAddress((void**)&p_keys, g_keys);
    cudaGetSymbolAddress((void**)&p_quer, g_quer);
    cudaGetSymbolAddress((void**)&p_vals, g_vals);
    cudaGetSymbolAddress((void**)&p_att,  g_att);
    cudaGetSymbolAddress((void**)&p_attv, g_attv);

    const long sCat = (long)CKC * HW;
    const long sQ   = (long)CQC * HW;
    const long sO   = (long)COC * HW;
    const long sV   = (long)VDIM * HW;
    const long sBig = (long)2 * CKC * HW;

    {
        const long total = (long)NB * CKC * HW;
        build_cat_kernel<<<(unsigned)((total + 255) / 256), 256>>>(x, ul, b, p_cat);
    }

    const dim3 gridS1(3, NB * 8);    // Cout<=169 -> 3 out-tiles of 64
    const dim3 gridS2K(6, NB * 8);   // Cout=338 -> 6
    const dim3 gridS2Q(6, NB * 8);   // Cout=332 -> 6
    const dim3 gridS2O(5, NB * 8);   // Cout=320 -> 5 (exact)

    // ---- GRN-K -> keys ----
    mma_gemm_celu<<<gridS1, 256>>>(p_cat, sCat, CKC, gkWi, nullptr, 0, 0, nullptr,
                                   gkbi, nullptr, CKC, p_h, sCat);
    mma_gemm_celu<<<gridS2K, 256>>>(p_h, sCat, CKC, gkWo, nullptr, 0, 0, nullptr,
                                    gkbo, nullptr, 2 * CKC, p_big, sBig);
    {
        const long t4 = (long)NB * CKC * (HW / 4);
        gate_kernel<<<(unsigned)((t4 + 255) / 256), 256>>>(p_big, sBig, CKC, p_cat, sCat, p_gout, sCat, t4);
    }
    proj_kernel<16><<<dim3(4, NB, 1), 256>>>(p_gout, CKC, nkW, nkb, p_keys, KDIM);

    // ---- GRN-Q -> queries (ul_b is a channel-offset view of cat) ----
    mma_gemm_celu<<<gridS1, 256>>>(p_cat + 3 * HW, sCat, CQC, gqWi, nullptr, 0, 0, nullptr,
                                   gqbi, nullptr, CQC, p_h, sQ);
    mma_gemm_celu<<<gridS2Q, 256>>>(p_h, sQ, CQC, gqWo, nullptr, 0, 0, nullptr,
                                    gqbo, nullptr, 2 * CQC, p_big, sBig);
    {
        const long t4 = (long)NB * CQC * (HW / 4);
        gate_kernel<<<(unsigned)((t4 + 255) / 256), 256>>>(p_big, sBig, CQC, p_cat + 3 * HW, sCat, p_gout, sQ, t4);
    }
    proj_kernel<16><<<dim3(4, NB, 1), 256>>>(p_gout, CQC, nqW, nqb, p_quer, KDIM);

    // ---- GRN-V -> values ----
    mma_gemm_celu<<<gridS1, 256>>>(p_cat, sCat, CKC, gvWi, nullptr, 0, 0, nullptr,
                                   gvbi, nullptr, CKC, p_h, sCat);
    mma_gemm_celu<<<gridS2K, 256>>>(p_h, sCat, CKC, gvWo, nullptr, 0, 0, nullptr,
                                    gvbo, nullptr, 2 * CKC, p_big, sBig);
    {
        const long t4 = (long)NB * CKC * (HW / 4);
        gate_kernel<<<(unsigned)((t4 + 255) / 256), 256>>>(p_big, sBig, CKC, p_cat, sCat, p_gout, sCat, t4);
    }
    proj_kernel<16><<<dim3(4, NB, 5), 256>>>(p_gout, CKC, nvW, nvb, p_vals, VDIM);

    // ---- attention ----
    qk_kernel<<<dim3(16, 16, NB), 256>>>(p_keys, p_quer, p_att);
    softmax_kernel<<<dim3(HW, NB), 256>>>(p_att);
    av_kernel<<<dim3(16, NB), 256>>>(p_att, p_vals, p_attv);

    // ---- GRN-O (aux = att_v), dual-input fused stage-1 ----
    mma_gemm_celu<<<gridS1, 256>>>(ul, sO, COC, goWi, p_attv, sV, VDIM, goWs,
                                   gobi, gobs, COC, p_h, sO);
    mma_gemm_celu<<<gridS2O, 256>>>(p_h, sO, COC, goWo, nullptr, 0, 0, nullptr,
                                    gobo, nullptr, 2 * COC, p_big, sBig);
    {
        const long t4 = (long)NB * COC * (HW / 4);
        gate_kernel<<<(unsigned)((t4 + 255) / 256), 256>>>(p_big, sBig, COC, ul, sO, out, sO, t4);
    }
}